// round 7
// baseline (speedup 1.0000x reference)
#include <cuda_runtime.h>
#include <cuda_bf16.h>

// Problem constants (fixed shapes from reference setup_inputs)
#define BT    16384      // B*T = 16*1024
#define HID   512
#define NP    30         // 3*K gaussian params per (b,t)
#define NU    600
#define NA    80
#define NK    10

// Scratch: transposed exp'ed params [p][bt].
// p in [0,10): a_k ; [10,20): -b_k ; [20,30): kappa_k
__device__ float g_par[NP * BT];

// ---------------------------------------------------------------------------
// Kernel 1: params = lstm_out @ W + bias, then exp, store transposed.
// Grid 128 blocks x 128 t-rows; 256 threads; thread owns 4t x 4p.
// A tile TRANSPOSED sA[h][t ^ 4*(h>>2)]: 2 LDS.128 + 16 FFMA per h.
// SOFTWARE PIPELINE: chunk c+1 is LDG'ed into registers while chunk c
// computes, hiding the ~600-cycle global latency behind 576 issue slots.
// ---------------------------------------------------------------------------
__global__ __launch_bounds__(256) void k1_gemm_exp(
    const float* __restrict__ lstm,
    const float* __restrict__ W,
    const float* __restrict__ bias)
{
    __shared__ float sA[32][132];    // [h][t-swizzled]
    __shared__ float sW[32][32];     // [h][p], p padded 30->32 (zeros)

    const int tid = threadIdx.x;
    const int t0  = blockIdx.x * 128;
    const int pg  = tid & 7;    // p in [pg*4, pg*4+4)
    const int tg  = tid >> 3;   // t in [tg*4, tg*4+4)

    float acc[4][4];
    #pragma unroll
    for (int i = 0; i < 4; i++)
        #pragma unroll
        for (int j = 0; j < 4; j++) acc[i][j] = 0.f;

    // zero the p=30,31 pad once (first compute happens after a sync)
    if (tid < 64) sW[tid >> 1][30 + (tid & 1)] = 0.f;

    // --- prologue: load chunk 0 into registers
    float4 va[4];
    float  wr[4];
    #pragma unroll
    for (int j = 0; j < 4; j++) {
        int idx = tid + 256 * j;
        int row = idx >> 3, c = idx & 7;
        va[j] = *reinterpret_cast<const float4*>(
            lstm + (size_t)(t0 + row) * HID + c * 4);
    }
    #pragma unroll
    for (int r = 0; r < 4; r++) {
        int idx = tid + 256 * r;
        if (idx < 32 * NP) wr[r] = W[idx];
    }

    #pragma unroll 1
    for (int ch = 0; ch < HID / 32; ch++) {
        __syncthreads();   // previous compute done reading smem
        // STS staged registers
        #pragma unroll
        for (int j = 0; j < 4; j++) {
            int idx = tid + 256 * j;
            int row = idx >> 3, c = idx & 7;
            int col = row ^ (c * 4);
            sA[4 * c + 0][col] = va[j].x;
            sA[4 * c + 1][col] = va[j].y;
            sA[4 * c + 2][col] = va[j].z;
            sA[4 * c + 3][col] = va[j].w;
        }
        #pragma unroll
        for (int r = 0; r < 4; r++) {
            int idx = tid + 256 * r;
            if (idx < 32 * NP) {
                int h = idx / NP;
                int p = idx - h * NP;
                sW[h][p] = wr[r];
            }
        }
        __syncthreads();

        // prefetch next chunk (overlaps compute below)
        if (ch + 1 < HID / 32) {
            int hc = (ch + 1) * 32;
            #pragma unroll
            for (int j = 0; j < 4; j++) {
                int idx = tid + 256 * j;
                int row = idx >> 3, c = idx & 7;
                va[j] = *reinterpret_cast<const float4*>(
                    lstm + (size_t)(t0 + row) * HID + hc + c * 4);
            }
            #pragma unroll
            for (int r = 0; r < 4; r++) {
                int idx = tid + 256 * r;
                if (idx < 32 * NP) wr[r] = W[hc * NP + idx];
            }
        }

        // compute current chunk
        #pragma unroll
        for (int h = 0; h < 32; h++) {
            float4 av = *reinterpret_cast<const float4*>(
                &sA[h][4 * (tg ^ (h >> 2))]);
            float4 wv = *reinterpret_cast<const float4*>(&sW[h][4 * pg]);
            acc[0][0] = fmaf(av.x, wv.x, acc[0][0]);
            acc[0][1] = fmaf(av.x, wv.y, acc[0][1]);
            acc[0][2] = fmaf(av.x, wv.z, acc[0][2]);
            acc[0][3] = fmaf(av.x, wv.w, acc[0][3]);
            acc[1][0] = fmaf(av.y, wv.x, acc[1][0]);
            acc[1][1] = fmaf(av.y, wv.y, acc[1][1]);
            acc[1][2] = fmaf(av.y, wv.z, acc[1][2]);
            acc[1][3] = fmaf(av.y, wv.w, acc[1][3]);
            acc[2][0] = fmaf(av.z, wv.x, acc[2][0]);
            acc[2][1] = fmaf(av.z, wv.y, acc[2][1]);
            acc[2][2] = fmaf(av.z, wv.z, acc[2][2]);
            acc[2][3] = fmaf(av.z, wv.w, acc[2][3]);
            acc[3][0] = fmaf(av.w, wv.x, acc[3][0]);
            acc[3][1] = fmaf(av.w, wv.y, acc[3][1]);
            acc[3][2] = fmaf(av.w, wv.z, acc[3][2]);
            acc[3][3] = fmaf(av.w, wv.w, acc[3][3]);
        }
    }

    // Epilogue: +bias, exp, negate b-block, store transposed [p][bt]
    #pragma unroll
    for (int i = 0; i < 4; i++) {
        int t = t0 + tg * 4 + i;
        #pragma unroll
        for (int j = 0; j < 4; j++) {
            int p = pg * 4 + j;
            if (p < NP) {
                float e = expf(acc[i][j] + bias[p]);
                if (p >= NK && p < 2 * NK) e = -e;   // store -b
                g_par[p * BT + t] = e;
            }
        }
    }
}

// ---------------------------------------------------------------------------
// Kernel 2: block of 256 threads owns 32 consecutive bt (same b: 32 | 1024).
// SHORT SERIAL CHAIN: one batched global-load phase (charseq rows [0,64) +
// params, MLP=9), one sync, phase1 (phi -> smem), one sync, phase2 (LDS+FFMA).
// Per-bl analytic cutoff computed per-thread (no block reduction). u >= 64
// tail falls back to global reads (analytically never taken: ucut <= ~30).
// ---------------------------------------------------------------------------
#define BPB    32        // bt's per block
#define UCHUNK 64
#define SUBS   8
#define APT    (NA / SUBS)   // 10 a-cols per sub-thread

__global__ __launch_bounds__(256) void k2_window(
    const float* __restrict__ charseq,
    float* __restrict__ out)
{
    __shared__ float spar[NP * BPB];          // [p*32+bl]  3.75 KB
    __shared__ float sphi[BPB][UCHUNK + 1];   // 8.1 KB
    __shared__ float scs[UCHUNK][NA];         // 20 KB: charseq rows [0,64)

    const int tid = threadIdx.x;
    const int bt0 = blockIdx.x * BPB;
    const int b   = bt0 >> 10;                // whole block shares b (32 | 1024)
    const float* cbase = charseq + (size_t)b * NU * NA;

    // ---- batched global loads (all LDGs independent, MLP ~ 9) ----
    float4 csr[5];                            // 64 rows x 20 f4 = 1280 = 256*5
    const float4* cb4 = reinterpret_cast<const float4*>(cbase);
    #pragma unroll
    for (int j = 0; j < 5; j++) csr[j] = cb4[tid + 256 * j];
    float pr[4];
    #pragma unroll
    for (int j = 0; j < 4; j++) {
        int idx = tid + 256 * j;
        if (idx < NP * BPB) {
            int p = idx >> 5, bl = idx & 31;
            pr[j] = g_par[p * BT + bt0 + bl];
        }
    }
    // ---- stage to smem ----
    float4* scs4 = reinterpret_cast<float4*>(&scs[0][0]);
    #pragma unroll
    for (int j = 0; j < 5; j++) scs4[tid + 256 * j] = csr[j];
    #pragma unroll
    for (int j = 0; j < 4; j++) {
        int idx = tid + 256 * j;
        if (idx < NP * BPB) spar[idx] = pr[j];
    }
    __syncthreads();

    const int bl  = tid >> 3;                 // bt_local 0..31
    const int sub = tid & 7;                  // a-col group 0..7

    float a[NK], nb[NK], kk[NK];
    #pragma unroll
    for (int k = 0; k < NK; k++) {
        a[k]  = spar[k * BPB + bl];
        nb[k] = spar[(NK + k) * BPB + bl];    // -b_k (negative)
        kk[k] = spar[(2 * NK + k) * BPB + bl];
    }

    // per-thread analytic cutoff: u > kappa + sqrt(48/b) => term < exp(-48)
    float cut = 1.f;
    #pragma unroll
    for (int k = 0; k < NK; k++)
        cut = fmaxf(cut, kk[k] + __fsqrt_rn(__fdividef(48.f, -nb[k])));
    const int ucut = min(NU, (int)cut + 1);

    // ---- phase 1: phi once per (bl, u), u striped by sub ----
    #pragma unroll
    for (int r = 0; r < UCHUNK / 8; r++) {
        int u = sub + 8 * r;
        if (u < ucut) {
            float uf  = (float)u;
            float phi = 0.f;
            #pragma unroll
            for (int k = 0; k < NK; k++) {
                float d = kk[k] - uf;
                phi += a[k] * __expf(nb[k] * d * d);
            }
            sphi[bl][u] = phi;
        }
    }
    __syncthreads();

    // ---- phase 2: pure LDS + FFMA over staged rows ----
    float acc[APT];
    #pragma unroll
    for (int j = 0; j < APT; j++) acc[j] = 0.f;

    const int uend = min(ucut, UCHUNK);
    for (int u = 0; u < uend; u++) {
        float phi = sphi[bl][u];
        const float* r = &scs[u][sub * APT];
        #pragma unroll
        for (int j = 0; j < APT / 2; j++) {
            float2 c = *reinterpret_cast<const float2*>(r + 2 * j);
            acc[2 * j + 0] = fmaf(phi, c.x, acc[2 * j + 0]);
            acc[2 * j + 1] = fmaf(phi, c.y, acc[2 * j + 1]);
        }
    }

    // tail u >= 64: analytically unreachable for this data; correct fallback
    for (int u = UCHUNK; u < ucut; u++) {
        float uf  = (float)u;
        float phi = 0.f;
        #pragma unroll
        for (int k = 0; k < NK; k++) {
            float d = kk[k] - uf;
            phi += a[k] * __expf(nb[k] * d * d);
        }
        const float* r = cbase + (size_t)u * NA + sub * APT;
        #pragma unroll
        for (int j = 0; j < APT; j++)
            acc[j] = fmaf(phi, __ldg(r + j), acc[j]);
    }

    float2* op = reinterpret_cast<float2*>(out + (size_t)(bt0 + bl) * NA + sub * APT);
    #pragma unroll
    for (int j = 0; j < APT / 2; j++)
        op[j] = make_float2(acc[2 * j], acc[2 * j + 1]);
}

// ---------------------------------------------------------------------------
extern "C" void kernel_launch(void* const* d_in, const int* in_sizes, int n_in,
                              void* d_out, int out_size)
{
    const float* lstm = (const float*)d_in[0];   // [16,1024,512]
    const float* cs   = (const float*)d_in[1];   // [16,600,80]
    const float* W    = (const float*)d_in[2];   // [512,30]
    const float* bias = (const float*)d_in[3];   // [30]
    float* out = (float*)d_out;                  // [16,1024,80]

    (void)in_sizes; (void)n_in; (void)out_size;

    k1_gemm_exp<<<BT / 128, 256>>>(lstm, W, bias);
    k2_window<<<BT / BPB, 256>>>(cs, out);
}

// round 9
// speedup vs baseline: 1.4618x; 1.4618x over previous
#include <cuda_runtime.h>
#include <cuda_bf16.h>
#include <cstdint>

// Problem constants (fixed shapes)
#define BT    16384      // B*T
#define HID   512
#define NP    30
#define NU    600
#define NA    80
#define NK    10

// Scratch: transposed exp'ed params [p][bt].
// p in [0,10): a_k ; [10,20): -b_k ; [20,30): kappa_k
__device__ float g_par[NP * BT];

__device__ __forceinline__ uint32_t smem_u32(const void* p) {
    return (uint32_t)__cvta_generic_to_shared(p);
}
__device__ __forceinline__ void ldsm_x4(uint32_t& r0, uint32_t& r1,
                                        uint32_t& r2, uint32_t& r3, uint32_t addr) {
    asm volatile("ldmatrix.sync.aligned.m8n8.x4.shared.b16 {%0,%1,%2,%3}, [%4];"
                 : "=r"(r0), "=r"(r1), "=r"(r2), "=r"(r3) : "r"(addr));
}
__device__ __forceinline__ void mma_bf16(float* c, const uint32_t* a,
                                         uint32_t b0, uint32_t b1) {
    asm volatile(
        "mma.sync.aligned.m16n8k16.row.col.f32.bf16.bf16.f32 "
        "{%0,%1,%2,%3}, {%4,%5,%6,%7}, {%8,%9}, {%0,%1,%2,%3};"
        : "+f"(c[0]), "+f"(c[1]), "+f"(c[2]), "+f"(c[3])
        : "r"(a[0]), "r"(a[1]), "r"(a[2]), "r"(a[3]), "r"(b0), "r"(b1));
}
__device__ __forceinline__ uint32_t pack_bf16(float x, float y) {
    return (uint32_t)__bfloat16_as_ushort(__float2bfloat16(x)) |
           ((uint32_t)__bfloat16_as_ushort(__float2bfloat16(y)) << 16);
}

// ---------------------------------------------------------------------------
// Kernel 1 (HMMA mma.sync): params = lstm @ W + bias -> exp -> g_par.
// 128 CTAs x 128 t-rows; 256 threads (8 warps). M=128, N=32 (30+2 pad),
// K=512 in 8 chunks of 64. fp32 via 3-term bf16 split: Ah*Wh + Ah*Wl + Al*Wh
// (missing Al*Wl ~ 2^-17 relative). Warp w owns m-rows [w*16, w*16+16) x all
// 4 n8-tiles. Smem stride 72 bf16 (144B): ldmatrix 8-row addresses hit 8
// distinct 16B bank columns (144 mod 128 = 16) -> conflict-free LDSM.
// A chunk c+1 prefetched into registers during compute of chunk c.
// ---------------------------------------------------------------------------
#define K1T    256
#define CHUNK  64
#define NCH    (HID / CHUNK)   // 8
#define ASTR   72              // smem row stride in bf16 elems (144 B)

__global__ __launch_bounds__(K1T) void k1_hmma(
    const float* __restrict__ lstm,
    const float* __restrict__ W,
    const float* __restrict__ bias)
{
    __shared__ __align__(16) __nv_bfloat16 sAh[128 * ASTR];  // 18 KB
    __shared__ __align__(16) __nv_bfloat16 sAl[128 * ASTR];  // 18 KB
    __shared__ __align__(16) __nv_bfloat16 sBh[32 * ASTR];   // 4.5 KB
    __shared__ __align__(16) __nv_bfloat16 sBl[32 * ASTR];   // 4.5 KB

    const int tid = threadIdx.x;
    const int wid = tid >> 5;
    const int lid = tid & 31;
    const int t0  = blockIdx.x * 128;
    const int m0  = wid * 16;

    float acc[4][4];
    #pragma unroll
    for (int n = 0; n < 4; n++)
        #pragma unroll
        for (int j = 0; j < 4; j++) acc[n][j] = 0.f;

    // ldmatrix lane addresses (element offsets; fixed per thread)
    const int a_row = m0 + (lid & 15);
    const int a_c8  = (lid & 16) ? 8 : 0;
    const uint32_t aBh = smem_u32(sAh) + (uint32_t)(a_row * ASTR + a_c8) * 2;
    const uint32_t aBl = smem_u32(sAl) + (uint32_t)(a_row * ASTR + a_c8) * 2;
    const int b_k8  = (lid & 8) ? 8 : 0;
    const int b_n   = (lid & 7) + ((lid & 16) ? 8 : 0);   // within 16-n pair
    const uint32_t bBh = smem_u32(sBh) + (uint32_t)(b_n * ASTR + b_k8) * 2;
    const uint32_t bBl = smem_u32(sBl) + (uint32_t)(b_n * ASTR + b_k8) * 2;

    // ---- prologue: prefetch chunk 0
    float4 va[8];
    float  wv[8];
    #pragma unroll
    for (int j = 0; j < 8; j++) {
        int idx = tid + K1T * j;               // 0..2047
        int row = idx >> 4, c4 = idx & 15;
        va[j] = *reinterpret_cast<const float4*>(
            lstm + (size_t)(t0 + row) * HID + c4 * 4);
    }
    #pragma unroll
    for (int j = 0; j < 8; j++) {
        int idx = tid + K1T * j;               // 0..2047
        int n = idx & 31, k = idx >> 5;
        wv[j] = (n < NP) ? W[(size_t)k * NP + n] : 0.f;
    }

    #pragma unroll 1
    for (int ch = 0; ch < NCH; ch++) {
        __syncthreads();    // previous compute done reading smem
        // ---- STS staged registers (convert f32 -> bf16 hi/lo)
        #pragma unroll
        for (int j = 0; j < 8; j++) {
            int idx = tid + K1T * j;
            int row = idx >> 4, c4 = idx & 15;
            float4 v = va[j];
            float hx = __bfloat162float(__float2bfloat16(v.x));
            float hy = __bfloat162float(__float2bfloat16(v.y));
            float hz = __bfloat162float(__float2bfloat16(v.z));
            float hw = __bfloat162float(__float2bfloat16(v.w));
            uint2 hp = make_uint2(pack_bf16(v.x, v.y), pack_bf16(v.z, v.w));
            uint2 lp = make_uint2(pack_bf16(v.x - hx, v.y - hy),
                                  pack_bf16(v.z - hz, v.w - hw));
            *reinterpret_cast<uint2*>(&sAh[row * ASTR + c4 * 4]) = hp;
            *reinterpret_cast<uint2*>(&sAl[row * ASTR + c4 * 4]) = lp;
        }
        #pragma unroll
        for (int j = 0; j < 8; j++) {
            int idx = tid + K1T * j;
            int n = idx & 31, k = idx >> 5;
            float f = wv[j];
            float h = __bfloat162float(__float2bfloat16(f));
            sBh[n * ASTR + k] = __float2bfloat16(f);
            sBl[n * ASTR + k] = __float2bfloat16(f - h);
        }
        __syncthreads();

        // ---- prefetch next chunk (overlaps MMA compute below)
        if (ch + 1 < NCH) {
            int k0 = (ch + 1) * CHUNK;
            #pragma unroll
            for (int j = 0; j < 8; j++) {
                int idx = tid + K1T * j;
                int row = idx >> 4, c4 = idx & 15;
                va[j] = *reinterpret_cast<const float4*>(
                    lstm + (size_t)(t0 + row) * HID + k0 + c4 * 4);
            }
            #pragma unroll
            for (int j = 0; j < 8; j++) {
                int idx = tid + K1T * j;
                int n = idx & 31, k = idx >> 5;
                wv[j] = (n < NP) ? W[(size_t)(k0 + k) * NP + n] : 0.f;
            }
        }

        // ---- compute: 4 k-steps of 16
        #pragma unroll
        for (int ks = 0; ks < 4; ks++) {
            uint32_t koff = (uint32_t)(ks * 16) * 2;   // bytes
            uint32_t ah[4], al[4];
            ldsm_x4(ah[0], ah[1], ah[2], ah[3], aBh + koff);
            ldsm_x4(al[0], al[1], al[2], al[3], aBl + koff);
            #pragma unroll
            for (int pr = 0; pr < 2; pr++) {           // n-tile pairs
                uint32_t poff = (uint32_t)(pr * 16 * ASTR) * 2 + koff;
                uint32_t bh[4], bl[4];
                ldsm_x4(bh[0], bh[1], bh[2], bh[3], bBh + poff);
                ldsm_x4(bl[0], bl[1], bl[2], bl[3], bBl + poff);
                mma_bf16(acc[2 * pr],     ah, bh[0], bh[1]);
                mma_bf16(acc[2 * pr],     ah, bl[0], bl[1]);
                mma_bf16(acc[2 * pr],     al, bh[0], bh[1]);
                mma_bf16(acc[2 * pr + 1], ah, bh[2], bh[3]);
                mma_bf16(acc[2 * pr + 1], ah, bl[2], bl[3]);
                mma_bf16(acc[2 * pr + 1], al, bh[2], bh[3]);
            }
        }
    }

    // ---- epilogue: +bias, exp, negate b-block, store transposed [p][bt]
    const int g  = lid >> 2;
    const int tg = lid & 3;
    #pragma unroll
    for (int nt = 0; nt < 4; nt++) {
        int p0 = nt * 8 + tg * 2;
        #pragma unroll
        for (int dp = 0; dp < 2; dp++) {
            int p = p0 + dp;
            if (p < NP) {
                float bz = bias[p];
                float e0 = expf(acc[nt][dp] + bz);       // row m0+g
                float e1 = expf(acc[nt][2 + dp] + bz);   // row m0+g+8
                if (p >= NK && p < 2 * NK) { e0 = -e0; e1 = -e1; }
                g_par[p * BT + t0 + m0 + g]     = e0;
                g_par[p * BT + t0 + m0 + g + 8] = e1;
            }
        }
    }
}

// ---------------------------------------------------------------------------
// Kernel 2: block of 256 threads owns 32 consecutive bt (same b).
// One batched load (charseq rows [0,32) + params), sync, phi->smem, sync,
// LDS+FFMA. Analytic ucut <= kappa_max + sqrt(48/b_min) ~ 27 < 32; u>=32
// tail reads global (correct fallback, analytically never taken).
// ---------------------------------------------------------------------------
#define BPB    32
#define UCHUNK 32
#define SUBS   8
#define APT    (NA / SUBS)   // 10

__global__ __launch_bounds__(256) void k2_window(
    const float* __restrict__ charseq,
    float* __restrict__ out)
{
    __shared__ float spar[NP * BPB];          // 3.75 KB
    __shared__ float sphi[BPB][UCHUNK + 1];   // 4.1 KB
    __shared__ float scs[UCHUNK][NA];         // 10 KB

    const int tid = threadIdx.x;
    const int bt0 = blockIdx.x * BPB;
    const int b   = bt0 >> 10;
    const float* cbase = charseq + (size_t)b * NU * NA;

    // batched independent LDGs (MLP ~ 7)
    float4 csr[3];
    const float4* cb4 = reinterpret_cast<const float4*>(cbase);
    #pragma unroll
    for (int j = 0; j < 3; j++) {
        int idx = tid + 256 * j;
        if (idx < UCHUNK * (NA / 4)) csr[j] = cb4[idx];   // 640 float4s
    }
    float pr[4];
    #pragma unroll
    for (int j = 0; j < 4; j++) {
        int idx = tid + 256 * j;
        if (idx < NP * BPB) {
            int p = idx >> 5, bl = idx & 31;
            pr[j] = g_par[p * BT + bt0 + bl];
        }
    }
    float4* scs4 = reinterpret_cast<float4*>(&scs[0][0]);
    #pragma unroll
    for (int j = 0; j < 3; j++) {
        int idx = tid + 256 * j;
        if (idx < UCHUNK * (NA / 4)) scs4[idx] = csr[j];
    }
    #pragma unroll
    for (int j = 0; j < 4; j++) {
        int idx = tid + 256 * j;
        if (idx < NP * BPB) spar[idx] = pr[j];
    }
    __syncthreads();

    const int bl  = tid >> 3;
    const int sub = tid & 7;

    float a[NK], nb[NK], kk[NK];
    #pragma unroll
    for (int k = 0; k < NK; k++) {
        a[k]  = spar[k * BPB + bl];
        nb[k] = spar[(NK + k) * BPB + bl];    // -b_k
        kk[k] = spar[(2 * NK + k) * BPB + bl];
    }

    float cut = 1.f;
    #pragma unroll
    for (int k = 0; k < NK; k++)
        cut = fmaxf(cut, kk[k] + __fsqrt_rn(__fdividef(48.f, -nb[k])));
    const int ucut = min(NU, (int)cut + 1);

    // phase 1: phi once per (bl,u), u striped by sub
    #pragma unroll
    for (int r = 0; r < UCHUNK / 8; r++) {
        int u = sub + 8 * r;
        if (u < ucut) {
            float uf  = (float)u;
            float phi = 0.f;
            #pragma unroll
            for (int k = 0; k < NK; k++) {
                float d = kk[k] - uf;
                phi += a[k] * __expf(nb[k] * d * d);
            }
            sphi[bl][u] = phi;
        }
    }
    __syncthreads();

    // phase 2: pure LDS + FFMA
    float acc[APT];
    #pragma unroll
    for (int j = 0; j < APT; j++) acc[j] = 0.f;

    const int uend = min(ucut, UCHUNK);
    for (int u = 0; u < uend; u++) {
        float phi = sphi[bl][u];
        const float* r = &scs[u][sub * APT];
        #pragma unroll
        for (int j = 0; j < APT / 2; j++) {
            float2 cv = *reinterpret_cast<const float2*>(r + 2 * j);
            acc[2 * j + 0] = fmaf(phi, cv.x, acc[2 * j + 0]);
            acc[2 * j + 1] = fmaf(phi, cv.y, acc[2 * j + 1]);
        }
    }
    // tail (analytically unreachable; correctness fallback)
    for (int u = UCHUNK; u < ucut; u++) {
        float uf  = (float)u;
        float phi = 0.f;
        #pragma unroll
        for (int k = 0; k < NK; k++) {
            float d = kk[k] - uf;
            phi += a[k] * __expf(nb[k] * d * d);
        }
        const float* r = cbase + (size_t)u * NA + sub * APT;
        #pragma unroll
        for (int j = 0; j < APT; j++)
            acc[j] = fmaf(phi, __ldg(r + j), acc[j]);
    }

    float2* op = reinterpret_cast<float2*>(out + (size_t)(bt0 + bl) * NA + sub * APT);
    #pragma unroll
    for (int j = 0; j < APT / 2; j++)
        op[j] = make_float2(acc[2 * j], acc[2 * j + 1]);
}

// ---------------------------------------------------------------------------
extern "C" void kernel_launch(void* const* d_in, const int* in_sizes, int n_in,
                              void* d_out, int out_size)
{
    const float* lstm = (const float*)d_in[0];   // [16,1024,512]
    const float* cs   = (const float*)d_in[1];   // [16,600,80]
    const float* W    = (const float*)d_in[2];   // [512,30]
    const float* bias = (const float*)d_in[3];   // [30]
    float* out = (float*)d_out;                  // [16,1024,80]

    (void)in_sizes; (void)n_in; (void)out_size;

    k1_hmma<<<BT / 128, K1T>>>(lstm, W, bias);
    k2_window<<<BT / BPB, 256>>>(cs, out);
}

// round 10
// speedup vs baseline: 1.6474x; 1.1269x over previous
#include <cuda_runtime.h>
#include <cuda_bf16.h>
#include <cstdint>

// Problem constants (fixed shapes)
#define BT    16384      // B*T
#define HID   512
#define NP    30
#define NU    600
#define NA    80
#define NK    10

// Scratch: transposed exp'ed params [p][bt].
__device__ float g_par[NP * BT];
// Pre-split W, transposed n-major: [n][k], n padded 30->32 with zeros.
__device__ __nv_bfloat16 g_wh[32 * HID];
__device__ __nv_bfloat16 g_wl[32 * HID];

__device__ __forceinline__ uint32_t smem_u32(const void* p) {
    return (uint32_t)__cvta_generic_to_shared(p);
}
__device__ __forceinline__ void ldsm_x4(uint32_t& r0, uint32_t& r1,
                                        uint32_t& r2, uint32_t& r3, uint32_t addr) {
    asm volatile("ldmatrix.sync.aligned.m8n8.x4.shared.b16 {%0,%1,%2,%3}, [%4];"
                 : "=r"(r0), "=r"(r1), "=r"(r2), "=r"(r3) : "r"(addr));
}
__device__ __forceinline__ void mma_bf16(float* c, const uint32_t* a,
                                         uint32_t b0, uint32_t b1) {
    asm volatile(
        "mma.sync.aligned.m16n8k16.row.col.f32.bf16.bf16.f32 "
        "{%0,%1,%2,%3}, {%4,%5,%6,%7}, {%8,%9}, {%0,%1,%2,%3};"
        : "+f"(c[0]), "+f"(c[1]), "+f"(c[2]), "+f"(c[3])
        : "r"(a[0]), "r"(a[1]), "r"(a[2]), "r"(a[3]), "r"(b0), "r"(b1));
}

// ---------------------------------------------------------------------------
// Kernel 0: split W (f32 [512][30]) into bf16 hi/lo, transposed [32][512].
// ---------------------------------------------------------------------------
__global__ __launch_bounds__(256) void k0_wsplit(const float* __restrict__ W)
{
    int idx = blockIdx.x * 256 + threadIdx.x;   // 0..16383
    int n = idx >> 9, k = idx & 511;
    float f = (n < NP) ? W[(size_t)k * NP + n] : 0.f;
    __nv_bfloat16 hi = __float2bfloat16(f);
    __nv_bfloat16 lo = __float2bfloat16(f - __bfloat162float(hi));
    g_wh[idx] = hi;
    g_wl[idx] = lo;
}

// ---------------------------------------------------------------------------
// Kernel 1 (HMMA): params = lstm @ W + bias -> exp -> g_par transposed.
// 256 CTAs x 64 t-rows; 128 threads (4 warps, warp owns 16 m-rows x 32 n).
// K=512 in 8 chunks of 64. fp32 via 3-term bf16 split (Ah*Wh+Ah*Wl+Al*Wh).
// W comes pre-split from k0 (LDG.128 -> STS.128, no cvt). A converted with
// paired bf16x2 cvts. Chunk c+1 prefetched into regs during compute of c.
// Smem stride 72 bf16 (144B): conflict-free ldmatrix (verified R9).
// ---------------------------------------------------------------------------
#define K1T    128
#define MROWS  64
#define CHUNK  64
#define NCH    (HID / CHUNK)   // 8
#define ASTR   72              // smem row stride in bf16 elems (144 B)

__global__ __launch_bounds__(K1T) void k1_hmma(
    const float* __restrict__ lstm,
    const float* __restrict__ bias)
{
    __shared__ __align__(16) __nv_bfloat16 sAh[MROWS * ASTR];  // 9 KB
    __shared__ __align__(16) __nv_bfloat16 sAl[MROWS * ASTR];  // 9 KB
    __shared__ __align__(16) __nv_bfloat16 sBh[32 * ASTR];     // 4.5 KB
    __shared__ __align__(16) __nv_bfloat16 sBl[32 * ASTR];     // 4.5 KB

    const int tid = threadIdx.x;
    const int wid = tid >> 5;
    const int lid = tid & 31;
    const int t0  = blockIdx.x * MROWS;
    const int m0  = wid * 16;

    float acc[4][4];
    #pragma unroll
    for (int n = 0; n < 4; n++)
        #pragma unroll
        for (int j = 0; j < 4; j++) acc[n][j] = 0.f;

    // ldmatrix lane addresses (fixed per thread)
    const int a_row = m0 + (lid & 15);
    const int a_c8  = (lid & 16) ? 8 : 0;
    const uint32_t aBh = smem_u32(sAh) + (uint32_t)(a_row * ASTR + a_c8) * 2;
    const uint32_t aBl = smem_u32(sAl) + (uint32_t)(a_row * ASTR + a_c8) * 2;
    const int b_k8  = (lid & 8) ? 8 : 0;
    const int b_n   = (lid & 7) + ((lid & 16) ? 8 : 0);
    const uint32_t bBh = smem_u32(sBh) + (uint32_t)(b_n * ASTR + b_k8) * 2;
    const uint32_t bBl = smem_u32(sBl) + (uint32_t)(b_n * ASTR + b_k8) * 2;

    // thread's W-copy slots: 256 uint4 per split per chunk, 2/thread
    // uint4 i covers n = i>>3, k8 = (i&7)*8
    const int wn0 = tid >> 3, wk0 = (tid & 7) * 8;
    const int wn1 = (tid + K1T) >> 3, wk1 = ((tid + K1T) & 7) * 8;

    // ---- prologue: prefetch chunk 0
    float4 va[8];
    uint4  wh0, wh1, wl0, wl1;
    #pragma unroll
    for (int j = 0; j < 8; j++) {
        int idx = tid + K1T * j;               // 0..1023
        int row = idx >> 4, c4 = idx & 15;
        va[j] = *reinterpret_cast<const float4*>(
            lstm + (size_t)(t0 + row) * HID + c4 * 4);
    }
    wh0 = *reinterpret_cast<const uint4*>(&g_wh[wn0 * HID + wk0]);
    wh1 = *reinterpret_cast<const uint4*>(&g_wh[wn1 * HID + wk1]);
    wl0 = *reinterpret_cast<const uint4*>(&g_wl[wn0 * HID + wk0]);
    wl1 = *reinterpret_cast<const uint4*>(&g_wl[wn1 * HID + wk1]);

    #pragma unroll 1
    for (int ch = 0; ch < NCH; ch++) {
        __syncthreads();    // previous compute done reading smem
        // ---- STS staged A (paired bf16x2 converts) + W (raw copy)
        #pragma unroll
        for (int j = 0; j < 8; j++) {
            int idx = tid + K1T * j;
            int row = idx >> 4, c4 = idx & 15;
            float4 v = va[j];
            __nv_bfloat162 h01 = __float22bfloat162_rn(make_float2(v.x, v.y));
            __nv_bfloat162 h23 = __float22bfloat162_rn(make_float2(v.z, v.w));
            float2 f01 = __bfloat1622float2(h01);
            float2 f23 = __bfloat1622float2(h23);
            __nv_bfloat162 l01 = __float22bfloat162_rn(
                make_float2(v.x - f01.x, v.y - f01.y));
            __nv_bfloat162 l23 = __float22bfloat162_rn(
                make_float2(v.z - f23.x, v.w - f23.y));
            *reinterpret_cast<uint2*>(&sAh[row * ASTR + c4 * 4]) =
                make_uint2(*reinterpret_cast<uint32_t*>(&h01),
                           *reinterpret_cast<uint32_t*>(&h23));
            *reinterpret_cast<uint2*>(&sAl[row * ASTR + c4 * 4]) =
                make_uint2(*reinterpret_cast<uint32_t*>(&l01),
                           *reinterpret_cast<uint32_t*>(&l23));
        }
        *reinterpret_cast<uint4*>(&sBh[wn0 * ASTR + wk0]) = wh0;
        *reinterpret_cast<uint4*>(&sBh[wn1 * ASTR + wk1]) = wh1;
        *reinterpret_cast<uint4*>(&sBl[wn0 * ASTR + wk0]) = wl0;
        *reinterpret_cast<uint4*>(&sBl[wn1 * ASTR + wk1]) = wl1;
        __syncthreads();

        // ---- prefetch next chunk (overlaps MMA compute below)
        if (ch + 1 < NCH) {
            int k0 = (ch + 1) * CHUNK;
            #pragma unroll
            for (int j = 0; j < 8; j++) {
                int idx = tid + K1T * j;
                int row = idx >> 4, c4 = idx & 15;
                va[j] = *reinterpret_cast<const float4*>(
                    lstm + (size_t)(t0 + row) * HID + k0 + c4 * 4);
            }
            wh0 = *reinterpret_cast<const uint4*>(&g_wh[wn0 * HID + k0 + wk0]);
            wh1 = *reinterpret_cast<const uint4*>(&g_wh[wn1 * HID + k0 + wk1]);
            wl0 = *reinterpret_cast<const uint4*>(&g_wl[wn0 * HID + k0 + wk0]);
            wl1 = *reinterpret_cast<const uint4*>(&g_wl[wn1 * HID + k0 + wk1]);
        }

        // ---- compute: 4 k-steps of 16
        #pragma unroll
        for (int ks = 0; ks < 4; ks++) {
            uint32_t koff = (uint32_t)(ks * 16) * 2;   // bytes
            uint32_t ah[4], al[4];
            ldsm_x4(ah[0], ah[1], ah[2], ah[3], aBh + koff);
            ldsm_x4(al[0], al[1], al[2], al[3], aBl + koff);
            #pragma unroll
            for (int pr = 0; pr < 2; pr++) {
                uint32_t poff = (uint32_t)(pr * 16 * ASTR) * 2 + koff;
                uint32_t bh[4], bl[4];
                ldsm_x4(bh[0], bh[1], bh[2], bh[3], bBh + poff);
                ldsm_x4(bl[0], bl[1], bl[2], bl[3], bBl + poff);
                mma_bf16(acc[2 * pr],     ah, bh[0], bh[1]);
                mma_bf16(acc[2 * pr],     ah, bl[0], bl[1]);
                mma_bf16(acc[2 * pr],     al, bh[0], bh[1]);
                mma_bf16(acc[2 * pr + 1], ah, bh[2], bh[3]);
                mma_bf16(acc[2 * pr + 1], ah, bl[2], bl[3]);
                mma_bf16(acc[2 * pr + 1], al, bh[2], bh[3]);
            }
        }
    }

    // ---- epilogue: +bias, exp, negate b-block, store transposed [p][bt]
    const int g  = lid >> 2;
    const int tg = lid & 3;
    #pragma unroll
    for (int nt = 0; nt < 4; nt++) {
        int p0 = nt * 8 + tg * 2;
        #pragma unroll
        for (int dp = 0; dp < 2; dp++) {
            int p = p0 + dp;
            if (p < NP) {
                float bz = bias[p];
                float e0 = expf(acc[nt][dp] + bz);       // row m0+g
                float e1 = expf(acc[nt][2 + dp] + bz);   // row m0+g+8
                if (p >= NK && p < 2 * NK) { e0 = -e0; e1 = -e1; }
                g_par[p * BT + t0 + m0 + g]     = e0;
                g_par[p * BT + t0 + m0 + g + 8] = e1;
            }
        }
    }
}

// ---------------------------------------------------------------------------
// Kernel 2: block of 256 threads owns 32 consecutive bt (same b).
// One batched load (charseq rows [0,32) + params), sync, phi->smem, sync,
// LDS+FFMA. Analytic ucut <= kappa_max + sqrt(48/b_min) ~ 27 < 32; u>=32
// tail reads global (correct fallback, analytically never taken).
// ---------------------------------------------------------------------------
#define BPB    32
#define UCHUNK 32
#define SUBS   8
#define APT    (NA / SUBS)   // 10

__global__ __launch_bounds__(256) void k2_window(
    const float* __restrict__ charseq,
    float* __restrict__ out)
{
    __shared__ float spar[NP * BPB];
    __shared__ float sphi[BPB][UCHUNK + 1];
    __shared__ float scs[UCHUNK][NA];

    const int tid = threadIdx.x;
    const int bt0 = blockIdx.x * BPB;
    const int b   = bt0 >> 10;
    const float* cbase = charseq + (size_t)b * NU * NA;

    float4 csr[3];
    const float4* cb4 = reinterpret_cast<const float4*>(cbase);
    #pragma unroll
    for (int j = 0; j < 3; j++) {
        int idx = tid + 256 * j;
        if (idx < UCHUNK * (NA / 4)) csr[j] = cb4[idx];
    }
    float pr[4];
    #pragma unroll
    for (int j = 0; j < 4; j++) {
        int idx = tid + 256 * j;
        if (idx < NP * BPB) {
            int p = idx >> 5, bl = idx & 31;
            pr[j] = g_par[p * BT + bt0 + bl];
        }
    }
    float4* scs4 = reinterpret_cast<float4*>(&scs[0][0]);
    #pragma unroll
    for (int j = 0; j < 3; j++) {
        int idx = tid + 256 * j;
        if (idx < UCHUNK * (NA / 4)) scs4[idx] = csr[j];
    }
    #pragma unroll
    for (int j = 0; j < 4; j++) {
        int idx = tid + 256 * j;
        if (idx < NP * BPB) spar[idx] = pr[j];
    }
    __syncthreads();

    const int bl  = tid >> 3;
    const int sub = tid & 7;

    float a[NK], nb[NK], kk[NK];
    #pragma unroll
    for (int k = 0; k < NK; k++) {
        a[k]  = spar[k * BPB + bl];
        nb[k] = spar[(NK + k) * BPB + bl];
        kk[k] = spar[(2 * NK + k) * BPB + bl];
    }

    float cut = 1.f;
    #pragma unroll
    for (int k = 0; k < NK; k++)
        cut = fmaxf(cut, kk[k] + __fsqrt_rn(__fdividef(48.f, -nb[k])));
    const int ucut = min(NU, (int)cut + 1);

    #pragma unroll
    for (int r = 0; r < UCHUNK / 8; r++) {
        int u = sub + 8 * r;
        if (u < ucut) {
            float uf  = (float)u;
            float phi = 0.f;
            #pragma unroll
            for (int k = 0; k < NK; k++) {
                float d = kk[k] - uf;
                phi += a[k] * __expf(nb[k] * d * d);
            }
            sphi[bl][u] = phi;
        }
    }
    __syncthreads();

    float acc[APT];
    #pragma unroll
    for (int j = 0; j < APT; j++) acc[j] = 0.f;

    const int uend = min(ucut, UCHUNK);
    for (int u = 0; u < uend; u++) {
        float phi = sphi[bl][u];
        const float* r = &scs[u][sub * APT];
        #pragma unroll
        for (int j = 0; j < APT / 2; j++) {
            float2 cv = *reinterpret_cast<const float2*>(r + 2 * j);
            acc[2 * j + 0] = fmaf(phi, cv.x, acc[2 * j + 0]);
            acc[2 * j + 1] = fmaf(phi, cv.y, acc[2 * j + 1]);
        }
    }
    for (int u = UCHUNK; u < ucut; u++) {
        float uf  = (float)u;
        float phi = 0.f;
        #pragma unroll
        for (int k = 0; k < NK; k++) {
            float d = kk[k] - uf;
            phi += a[k] * __expf(nb[k] * d * d);
        }
        const float* r = cbase + (size_t)u * NA + sub * APT;
        #pragma unroll
        for (int j = 0; j < APT; j++)
            acc[j] = fmaf(phi, __ldg(r + j), acc[j]);
    }

    float2* op = reinterpret_cast<float2*>(out + (size_t)(bt0 + bl) * NA + sub * APT);
    #pragma unroll
    for (int j = 0; j < APT / 2; j++)
        op[j] = make_float2(acc[2 * j], acc[2 * j + 1]);
}

// ---------------------------------------------------------------------------
extern "C" void kernel_launch(void* const* d_in, const int* in_sizes, int n_in,
                              void* d_out, int out_size)
{
    const float* lstm = (const float*)d_in[0];   // [16,1024,512]
    const float* cs   = (const float*)d_in[1];   // [16,600,80]
    const float* W    = (const float*)d_in[2];   // [512,30]
    const float* bias = (const float*)d_in[3];   // [30]
    float* out = (float*)d_out;                  // [16,1024,80]

    (void)in_sizes; (void)n_in; (void)out_size;

    k0_wsplit<<<64, 256>>>(W);
    k1_hmma<<<BT / MROWS, K1T>>>(lstm, bias);
    k2_window<<<BT / BPB, 256>>>(cs, out);
}

// round 11
// speedup vs baseline: 1.6544x; 1.0042x over previous
#include <cuda_runtime.h>
#include <cuda_bf16.h>
#include <cstdint>

// Problem constants (fixed shapes)
#define BT    16384      // B*T
#define HID   512
#define NP    30
#define NU    600
#define NA    80
#define NK    10

// Pre-split W, transposed n-major: [n][k], n padded 30->32 with zeros.
__device__ __nv_bfloat16 g_wh[32 * HID];
__device__ __nv_bfloat16 g_wl[32 * HID];

__device__ __forceinline__ uint32_t smem_u32(const void* p) {
    return (uint32_t)__cvta_generic_to_shared(p);
}
__device__ __forceinline__ void ldsm_x4(uint32_t& r0, uint32_t& r1,
                                        uint32_t& r2, uint32_t& r3, uint32_t addr) {
    asm volatile("ldmatrix.sync.aligned.m8n8.x4.shared.b16 {%0,%1,%2,%3}, [%4];"
                 : "=r"(r0), "=r"(r1), "=r"(r2), "=r"(r3) : "r"(addr));
}
__device__ __forceinline__ void mma_bf16(float* c, const uint32_t* a,
                                         uint32_t b0, uint32_t b1) {
    asm volatile(
        "mma.sync.aligned.m16n8k16.row.col.f32.bf16.bf16.f32 "
        "{%0,%1,%2,%3}, {%4,%5,%6,%7}, {%8,%9}, {%0,%1,%2,%3};"
        : "+f"(c[0]), "+f"(c[1]), "+f"(c[2]), "+f"(c[3])
        : "r"(a[0]), "r"(a[1]), "r"(a[2]), "r"(a[3]), "r"(b0), "r"(b1));
}

// ---------------------------------------------------------------------------
// Kernel 0: split W (f32 [512][30]) into bf16 hi/lo, transposed [32][512].
// ---------------------------------------------------------------------------
__global__ __launch_bounds__(256) void k0_wsplit(const float* __restrict__ W)
{
    int idx = blockIdx.x * 256 + threadIdx.x;   // 0..16383
    int n = idx >> 9, k = idx & 511;
    float f = (n < NP) ? W[(size_t)k * NP + n] : 0.f;
    __nv_bfloat16 hi = __float2bfloat16(f);
    __nv_bfloat16 lo = __float2bfloat16(f - __bfloat162float(hi));
    g_wh[idx] = hi;
    g_wl[idx] = lo;
}

// ---------------------------------------------------------------------------
// FUSED kernel: per CTA of 64 bt rows:
//   Phase A: HMMA GEMM (M=64, N=32 pad, K=512 in 8 chunks; 3-term bf16 split,
//            reg-prefetch pipeline; verified R10) -> exp'ed params to SMEM.
//   Phase B: gaussian window + char mix for the same 64 bt (phi once per
//            (bt,u) into smem; charseq rows [0,32) staged; analytic cutoff
//            with global-read tail fallback for ucut>32).
// No g_par global roundtrip; scs/sphi alias the A-tile smem region.
// ---------------------------------------------------------------------------
#define K1T    128
#define MROWS  64
#define CHUNK  64
#define NCH    (HID / CHUNK)   // 8
#define ASTR   72              // smem row stride in bf16 elems (144 B)

// static smem layout (bytes)
#define OFF_AH   0              // 64*72*2   = 9216   (GEMM)
#define OFF_AL   9216           // 9216              (GEMM)
#define OFF_SCS  0              // 32*80*4   = 10240  (phase B, aliases sA)
#define OFF_SPHI 10240          // 64*33*4   = 8448   (phase B, aliases sA)
#define OFF_BH   18688          // 32*72*2   = 4608
#define OFF_BL   23296          // 4608
#define OFF_SPAR 27904          // 30*64*4   = 7680
#define OFF_CUT  35584          // 64*4      = 256
#define SMEM_TOT 35840

__global__ __launch_bounds__(K1T) void k_fused(
    const float* __restrict__ lstm,
    const float* __restrict__ bias,
    const float* __restrict__ charseq,
    float* __restrict__ out)
{
    __shared__ __align__(16) char buf[SMEM_TOT];
    __nv_bfloat16* sAh = reinterpret_cast<__nv_bfloat16*>(buf + OFF_AH);
    __nv_bfloat16* sAl = reinterpret_cast<__nv_bfloat16*>(buf + OFF_AL);
    __nv_bfloat16* sBh = reinterpret_cast<__nv_bfloat16*>(buf + OFF_BH);
    __nv_bfloat16* sBl = reinterpret_cast<__nv_bfloat16*>(buf + OFF_BL);
    float*         spar = reinterpret_cast<float*>(buf + OFF_SPAR);  // [p][bl]

    const int tid = threadIdx.x;
    const int wid = tid >> 5;
    const int lid = tid & 31;
    const int t0  = blockIdx.x * MROWS;
    const int m0  = wid * 16;

    // ======================= Phase A: GEMM =======================
    float acc[4][4];
    #pragma unroll
    for (int n = 0; n < 4; n++)
        #pragma unroll
        for (int j = 0; j < 4; j++) acc[n][j] = 0.f;

    const int a_row = m0 + (lid & 15);
    const int a_c8  = (lid & 16) ? 8 : 0;
    const uint32_t aBh = smem_u32(sAh) + (uint32_t)(a_row * ASTR + a_c8) * 2;
    const uint32_t aBl = smem_u32(sAl) + (uint32_t)(a_row * ASTR + a_c8) * 2;
    const int b_k8  = (lid & 8) ? 8 : 0;
    const int b_n   = (lid & 7) + ((lid & 16) ? 8 : 0);
    const uint32_t bBh = smem_u32(sBh) + (uint32_t)(b_n * ASTR + b_k8) * 2;
    const uint32_t bBl = smem_u32(sBl) + (uint32_t)(b_n * ASTR + b_k8) * 2;

    const int wn0 = tid >> 3, wk0 = (tid & 7) * 8;
    const int wn1 = (tid + K1T) >> 3, wk1 = ((tid + K1T) & 7) * 8;

    float4 va[8];
    uint4  wh0, wh1, wl0, wl1;
    #pragma unroll
    for (int j = 0; j < 8; j++) {
        int idx = tid + K1T * j;
        int row = idx >> 4, c4 = idx & 15;
        va[j] = *reinterpret_cast<const float4*>(
            lstm + (size_t)(t0 + row) * HID + c4 * 4);
    }
    wh0 = *reinterpret_cast<const uint4*>(&g_wh[wn0 * HID + wk0]);
    wh1 = *reinterpret_cast<const uint4*>(&g_wh[wn1 * HID + wk1]);
    wl0 = *reinterpret_cast<const uint4*>(&g_wl[wn0 * HID + wk0]);
    wl1 = *reinterpret_cast<const uint4*>(&g_wl[wn1 * HID + wk1]);

    #pragma unroll 1
    for (int ch = 0; ch < NCH; ch++) {
        __syncthreads();
        #pragma unroll
        for (int j = 0; j < 8; j++) {
            int idx = tid + K1T * j;
            int row = idx >> 4, c4 = idx & 15;
            float4 v = va[j];
            __nv_bfloat162 h01 = __float22bfloat162_rn(make_float2(v.x, v.y));
            __nv_bfloat162 h23 = __float22bfloat162_rn(make_float2(v.z, v.w));
            float2 f01 = __bfloat1622float2(h01);
            float2 f23 = __bfloat1622float2(h23);
            __nv_bfloat162 l01 = __float22bfloat162_rn(
                make_float2(v.x - f01.x, v.y - f01.y));
            __nv_bfloat162 l23 = __float22bfloat162_rn(
                make_float2(v.z - f23.x, v.w - f23.y));
            *reinterpret_cast<uint2*>(&sAh[row * ASTR + c4 * 4]) =
                make_uint2(*reinterpret_cast<uint32_t*>(&h01),
                           *reinterpret_cast<uint32_t*>(&h23));
            *reinterpret_cast<uint2*>(&sAl[row * ASTR + c4 * 4]) =
                make_uint2(*reinterpret_cast<uint32_t*>(&l01),
                           *reinterpret_cast<uint32_t*>(&l23));
        }
        *reinterpret_cast<uint4*>(&sBh[wn0 * ASTR + wk0]) = wh0;
        *reinterpret_cast<uint4*>(&sBh[wn1 * ASTR + wk1]) = wh1;
        *reinterpret_cast<uint4*>(&sBl[wn0 * ASTR + wk0]) = wl0;
        *reinterpret_cast<uint4*>(&sBl[wn1 * ASTR + wk1]) = wl1;
        __syncthreads();

        if (ch + 1 < NCH) {
            int k0 = (ch + 1) * CHUNK;
            #pragma unroll
            for (int j = 0; j < 8; j++) {
                int idx = tid + K1T * j;
                int row = idx >> 4, c4 = idx & 15;
                va[j] = *reinterpret_cast<const float4*>(
                    lstm + (size_t)(t0 + row) * HID + k0 + c4 * 4);
            }
            wh0 = *reinterpret_cast<const uint4*>(&g_wh[wn0 * HID + k0 + wk0]);
            wh1 = *reinterpret_cast<const uint4*>(&g_wh[wn1 * HID + k0 + wk1]);
            wl0 = *reinterpret_cast<const uint4*>(&g_wl[wn0 * HID + k0 + wk0]);
            wl1 = *reinterpret_cast<const uint4*>(&g_wl[wn1 * HID + k0 + wk1]);
        }

        #pragma unroll
        for (int ks = 0; ks < 4; ks++) {
            uint32_t koff = (uint32_t)(ks * 16) * 2;
            uint32_t ah[4], al[4];
            ldsm_x4(ah[0], ah[1], ah[2], ah[3], aBh + koff);
            ldsm_x4(al[0], al[1], al[2], al[3], aBl + koff);
            #pragma unroll
            for (int pr = 0; pr < 2; pr++) {
                uint32_t poff = (uint32_t)(pr * 16 * ASTR) * 2 + koff;
                uint32_t bh[4], bl[4];
                ldsm_x4(bh[0], bh[1], bh[2], bh[3], bBh + poff);
                ldsm_x4(bl[0], bl[1], bl[2], bl[3], bBl + poff);
                mma_bf16(acc[2 * pr],     ah, bh[0], bh[1]);
                mma_bf16(acc[2 * pr],     ah, bl[0], bl[1]);
                mma_bf16(acc[2 * pr],     al, bh[0], bh[1]);
                mma_bf16(acc[2 * pr + 1], ah, bh[2], bh[3]);
                mma_bf16(acc[2 * pr + 1], ah, bl[2], bl[3]);
                mma_bf16(acc[2 * pr + 1], al, bh[2], bh[3]);
            }
        }
    }

    // epilogue: +bias, exp, negate b-block, params -> SMEM spar[p][bl]
    {
        const int g  = lid >> 2;
        const int tg = lid & 3;
        #pragma unroll
        for (int nt = 0; nt < 4; nt++) {
            int p0 = nt * 8 + tg * 2;
            #pragma unroll
            for (int dp = 0; dp < 2; dp++) {
                int p = p0 + dp;
                if (p < NP) {
                    float bz = bias[p];
                    float e0 = expf(acc[nt][dp] + bz);
                    float e1 = expf(acc[nt][2 + dp] + bz);
                    if (p >= NK && p < 2 * NK) { e0 = -e0; e1 = -e1; }
                    spar[p * MROWS + m0 + g]     = e0;
                    spar[p * MROWS + m0 + g + 8] = e1;
                }
            }
        }
    }
    __syncthreads();   // spar complete; sA region now free for scs/sphi

    // ======================= Phase B: window =======================
    float* scs  = reinterpret_cast<float*>(buf + OFF_SCS);   // [32][80]
    float* sphi = reinterpret_cast<float*>(buf + OFF_SPHI);  // [64][33]
    int*   scut = reinterpret_cast<int*>(buf + OFF_CUT);     // [64]

    const int b = t0 >> 10;                   // 64 | 1024: whole CTA shares b
    const float* cbase = charseq + (size_t)b * NU * NA;

    // stage charseq rows [0,32): 640 float4, coalesced
    {
        const float4* cb4 = reinterpret_cast<const float4*>(cbase);
        float4* scs4 = reinterpret_cast<float4*>(scs);
        #pragma unroll
        for (int j = 0; j < 5; j++)
            scs4[tid + K1T * j] = cb4[tid + K1T * j];
    }

    // phi: thread handles bl = tid>>1, u striped by half = tid&1
    {
        const int bl = tid >> 1, half = tid & 1;
        float a[NK], nb[NK], kk[NK];
        #pragma unroll
        for (int k = 0; k < NK; k++) {
            a[k]  = spar[k * MROWS + bl];
            nb[k] = spar[(NK + k) * MROWS + bl];      // -b_k
            kk[k] = spar[(2 * NK + k) * MROWS + bl];
        }
        // u > kappa + sqrt(48/b): term < exp(-48) ~ 1.4e-21 -> truncate
        float cut = 1.f;
        #pragma unroll
        for (int k = 0; k < NK; k++)
            cut = fmaxf(cut, kk[k] + __fsqrt_rn(__fdividef(48.f, -nb[k])));
        int ucut = min(NU, (int)cut + 1);
        if (half == 0) scut[bl] = ucut;
        #pragma unroll
        for (int r = 0; r < 16; r++) {
            int u = half + 2 * r;
            if (u < ucut) {
                float uf  = (float)u;
                float phi = 0.f;
                #pragma unroll
                for (int k = 0; k < NK; k++) {
                    float d = kk[k] - uf;
                    phi += a[k] * __expf(nb[k] * d * d);
                }
                sphi[bl * 33 + u] = phi;
            }
        }
    }
    __syncthreads();

    // accumulate: two passes of 32 bl; thread = (bl, sub), sub owns 20 a-cols
    #pragma unroll 1
    for (int pass = 0; pass < 2; pass++) {
        const int bl  = (tid >> 2) + 32 * pass;
        const int sub = tid & 3;
        const int ucut = scut[bl];
        const int uend = min(ucut, 32);

        float acc2[20];
        #pragma unroll
        for (int j = 0; j < 20; j++) acc2[j] = 0.f;

        for (int u = 0; u < uend; u++) {
            float phi = sphi[bl * 33 + u];
            const float* r = scs + u * NA + sub * 20;
            #pragma unroll
            for (int j = 0; j < 5; j++) {
                float4 c = *reinterpret_cast<const float4*>(r + 4 * j);
                acc2[4 * j + 0] = fmaf(phi, c.x, acc2[4 * j + 0]);
                acc2[4 * j + 1] = fmaf(phi, c.y, acc2[4 * j + 1]);
                acc2[4 * j + 2] = fmaf(phi, c.z, acc2[4 * j + 2]);
                acc2[4 * j + 3] = fmaf(phi, c.w, acc2[4 * j + 3]);
            }
        }
        // tail u >= 32 (analytically unreachable; correctness fallback)
        if (ucut > 32) {
            float a[NK], nb[NK], kk[NK];
            #pragma unroll
            for (int k = 0; k < NK; k++) {
                a[k]  = spar[k * MROWS + bl];
                nb[k] = spar[(NK + k) * MROWS + bl];
                kk[k] = spar[(2 * NK + k) * MROWS + bl];
            }
            for (int u = 32; u < ucut; u++) {
                float uf  = (float)u;
                float phi = 0.f;
                #pragma unroll
                for (int k = 0; k < NK; k++) {
                    float d = kk[k] - uf;
                    phi += a[k] * __expf(nb[k] * d * d);
                }
                const float* r = cbase + (size_t)u * NA + sub * 20;
                #pragma unroll
                for (int j = 0; j < 20; j++)
                    acc2[j] = fmaf(phi, __ldg(r + j), acc2[j]);
            }
        }

        float4* op = reinterpret_cast<float4*>(
            out + (size_t)(t0 + bl) * NA + sub * 20);
        #pragma unroll
        for (int j = 0; j < 5; j++)
            op[j] = make_float4(acc2[4 * j], acc2[4 * j + 1],
                                acc2[4 * j + 2], acc2[4 * j + 3]);
    }
}

// ---------------------------------------------------------------------------
extern "C" void kernel_launch(void* const* d_in, const int* in_sizes, int n_in,
                              void* d_out, int out_size)
{
    const float* lstm = (const float*)d_in[0];   // [16,1024,512]
    const float* cs   = (const float*)d_in[1];   // [16,600,80]
    const float* W    = (const float*)d_in[2];   // [512,30]
    const float* bias = (const float*)d_in[3];   // [30]
    float* out = (float*)d_out;                  // [16,1024,80]

    (void)in_sizes; (void)n_in; (void)out_size;

    k0_wsplit<<<64, 256>>>(W);
    k_fused<<<BT / MROWS, K1T>>>(lstm, bias, cs, out);
}